// round 16
// baseline (speedup 1.0000x reference)
#include <cuda_runtime.h>
#include <cuda_bf16.h>
#include <math.h>
#include <cstdint>
#include <cstddef>

typedef __nv_bfloat16 bf16;

// Problem constants
#define BB   32
#define NN_  4096
#define PP   256
#define DX_  128
#define DU_  64
#define DK_  128
#define DV_  128
#define DOUT_ 256
#define HH   512
#define TOK  (BB*NN_)   // 131072
#define BPQ  (BB*PP)    // 8192
#define KSPLIT 8

// ---------------- single arena (packed b2 = 4 B/elem) ------------------------
#define OFF_XU2   0ull
#define OFF_H1S   100663296ull
#define OFF_H2S   369098752ull
#define OFF_SS    OFF_H2S            /* aliases h2s (dead after V-MLP) */
#define OFF_KS    637534208ull
#define OFF_VS    704643072ull
#define OFF_PT    771751936ull
#define OFF_WS    805306368ull
#define OFF_Q     809893888ull
#define OFF_QS    814088192ull
#define OFF_POOLS 818282496ull
#define OFF_DQ    822476800ull
#define OFF_LW    826671104ull
#define ARENA_BYTES 827195392ull

__device__ __align__(1024) char g_arena[ARENA_BYTES];

// weight plane offsets (words) inside ws
#define WOFF_KW1 0u
#define WOFF_KW2 65536u
#define WOFF_KW3 327680u
#define WOFF_VW1 393216u
#define WOFF_VW2 491520u
#define WOFF_VW3 753664u
#define WOFF_RW1 819200u
#define WOFF_RW2 884736u
#define WOFF_FW1 1015808u
#define WOFF_FW2 1081344u

// ---------------- helpers ----------------------------------------------------
// gelu(tanh approx) via expf: gelu = x * t/(t+1), t = exp(2*0.79788456*(x+0.044715x^3))
__device__ __forceinline__ float gelu_tanh(float x) {
    float u = 1.5957691216057308f * (x + 0.044715f * x * x * x);
    u = fminf(fmaxf(u, -30.f), 30.f);
    float t = __expf(u);
    return x * __fdividef(t, t + 1.f);
}
__device__ __forceinline__ float warp_sum(float v) {
#pragma unroll
    for (int o = 16; o > 0; o >>= 1) v += __shfl_xor_sync(0xffffffffu, v, o);
    return v;
}
__device__ __forceinline__ float warp_max(float v) {
#pragma unroll
    for (int o = 16; o > 0; o >>= 1) v = fmaxf(v, __shfl_xor_sync(0xffffffffu, v, o));
    return v;
}
// pack x as (bf16 hi | bf16 lo<<16); x ~= hi + lo. Guards inf/nan (lo = 0).
__device__ __forceinline__ unsigned pack_b2(float x) {
    bf16 hb = __float2bfloat16(x);
    float hf = __bfloat162float(hb);
    float r = x - hf;
    if (!(fabsf(hf) <= 3.38e38f)) r = 0.f;
    bf16 lb = __float2bfloat16(r);
    return (unsigned)__bfloat16_as_ushort(hb) |
           ((unsigned)__bfloat16_as_ushort(lb) << 16);
}
__device__ __forceinline__ float unpack_b2(unsigned w) {
    return __bfloat162float(__ushort_as_bfloat16((unsigned short)(w & 0xFFFFu)))
         + __bfloat162float(__ushort_as_bfloat16((unsigned short)(w >> 16)));
}
__device__ __forceinline__ void mma_bf16(float d[4], const unsigned a[4], const unsigned b[2]) {
    asm volatile(
        "mma.sync.aligned.m16n8k16.row.col.f32.bf16.bf16.f32 "
        "{%0,%1,%2,%3}, {%4,%5,%6,%7}, {%8,%9}, {%0,%1,%2,%3};\n"
        : "+f"(d[0]), "+f"(d[1]), "+f"(d[2]), "+f"(d[3])
        : "r"(a[0]), "r"(a[1]), "r"(a[2]), "r"(a[3]), "r"(b[0]), "r"(b[1]));
}
__device__ __forceinline__ unsigned smem_u32(const void* p) {
    return (unsigned)__cvta_generic_to_shared(p);
}
__device__ __forceinline__ void cp16(unsigned dst, const void* src) {
    asm volatile("cp.async.cg.shared.global [%0], [%1], 16;\n" :: "r"(dst), "l"(src));
}

// smem geometry (units = uint32 words); 3-stage ring, ONE barrier per k-tile
#define NSTAGE 3
#define A_STR 24
#define A_BUF (128*A_STR)            // 3072
template<bool TRB> struct BCfg;
template<> struct BCfg<false> { static constexpr int STR = 132; static constexpr int BUF = 16*132;  };
template<> struct BCfg<true>  { static constexpr int STR = 24;  static constexpr int BUF = 128*24;  };
#define SMEM_NN  ((NSTAGE*A_BUF + NSTAGE*BCfg<false>::BUF) * 4)  // 62208 B
#define SMEM_TRB ((NSTAGE*A_BUF + NSTAGE*BCfg<true>::BUF)  * 4)  // 73728 B

// =============================================================================
// 3xBF16 tensor-core GEMM core on packed (hi|lo) uint32 operands.
// 128x128 tile, BK=16, 256 threads, warps 2(m) x 4(n), 64x32 per warp.
// 3-stage ring, canonical ordering: wait -> sync -> issue(t+2) -> MMA(t).
// The single sync proves all warps retired MMA(t-1), making the write to
// buf (t+2)%3 == (t-1)%3 race-free without a trailing barrier.
// =============================================================================
template<bool TRB>
__device__ __forceinline__ void tc_core(
    const unsigned* __restrict__ Ag, int lda,
    const unsigned* __restrict__ Bg, int ldb,
    int K, int bm, int bn, float (&acc)[4][4][4],
    unsigned* As, unsigned* Bs)
{
    const int tid = threadIdx.x, lane = tid & 31;
    const int g = lane >> 2, t4 = lane & 3;
    const int warp = tid >> 5;
    const int m0 = (warp >> 2) * 64, n0 = (warp & 3) * 32;
    constexpr int BSTR = BCfg<TRB>::STR;
    constexpr int BBUF = BCfg<TRB>::BUF;

    auto issue = [&](int k0, int buf) {
#pragma unroll
        for (int i = 0; i < 2; i++) {
            int idx = tid + i * 256;
            int r = idx >> 2, q = (idx & 3) * 4;
            cp16(smem_u32(As + buf * A_BUF + r * A_STR + q),
                 Ag + (size_t)(bm + r) * lda + k0 + q);
        }
#pragma unroll
        for (int i = 0; i < 2; i++) {
            int idx = tid + i * 256;
            if (TRB) {
                int r = idx >> 2, q = (idx & 3) * 4;
                cp16(smem_u32(Bs + buf * BBUF + r * BSTR + q),
                     Bg + (size_t)(bn + r) * ldb + k0 + q);
            } else {
                int r = idx >> 5, q = (idx & 31) * 4;
                cp16(smem_u32(Bs + buf * BBUF + r * BSTR + q),
                     Bg + (size_t)(k0 + r) * ldb + bn + q);
            }
        }
        asm volatile("cp.async.commit_group;\n");
    };

    const int nt = K >> 4;
    issue(0, 0);
    if (nt > 1) issue(16, 1);
    int bt = 0;
    for (int t = 0; t < nt; t++) {
        if (t + 1 < nt) { asm volatile("cp.async.wait_group 1;\n"); }
        else            { asm volatile("cp.async.wait_group 0;\n"); }
        __syncthreads();
        if (t + 2 < nt) {
            int bi = bt + 2; if (bi >= NSTAGE) bi -= NSTAGE;
            issue((t + 2) << 4, bi);
        }
        const unsigned* Ab = As + bt * A_BUF;
        const unsigned* Bb = Bs + bt * BBUF;

        unsigned ah[4][4], al[4][4];
#pragma unroll
        for (int mi = 0; mi < 4; mi++) {
            int mr = m0 + mi * 16;
            uint2 w0 = *(const uint2*)&Ab[(mr + g    ) * A_STR + 2 * t4    ];
            uint2 w1 = *(const uint2*)&Ab[(mr + g + 8) * A_STR + 2 * t4    ];
            uint2 w2 = *(const uint2*)&Ab[(mr + g    ) * A_STR + 2 * t4 + 8];
            uint2 w3 = *(const uint2*)&Ab[(mr + g + 8) * A_STR + 2 * t4 + 8];
            ah[mi][0] = __byte_perm(w0.x, w0.y, 0x5410); al[mi][0] = __byte_perm(w0.x, w0.y, 0x7632);
            ah[mi][1] = __byte_perm(w1.x, w1.y, 0x5410); al[mi][1] = __byte_perm(w1.x, w1.y, 0x7632);
            ah[mi][2] = __byte_perm(w2.x, w2.y, 0x5410); al[mi][2] = __byte_perm(w2.x, w2.y, 0x7632);
            ah[mi][3] = __byte_perm(w3.x, w3.y, 0x5410); al[mi][3] = __byte_perm(w3.x, w3.y, 0x7632);
        }
#pragma unroll
        for (int ni = 0; ni < 4; ni++) {
            unsigned bh[2], bl[2];
            if (TRB) {
                int nr = n0 + ni * 8 + g;
                uint2 v0 = *(const uint2*)&Bb[nr * BSTR + 2 * t4    ];
                uint2 v1 = *(const uint2*)&Bb[nr * BSTR + 2 * t4 + 8];
                bh[0] = __byte_perm(v0.x, v0.y, 0x5410); bl[0] = __byte_perm(v0.x, v0.y, 0x7632);
                bh[1] = __byte_perm(v1.x, v1.y, 0x5410); bl[1] = __byte_perm(v1.x, v1.y, 0x7632);
            } else {
                int col = n0 + ni * 8 + g;
                unsigned x0 = Bb[(2 * t4    ) * BSTR + col];
                unsigned x1 = Bb[(2 * t4 + 1) * BSTR + col];
                unsigned x2 = Bb[(2 * t4 + 8) * BSTR + col];
                unsigned x3 = Bb[(2 * t4 + 9) * BSTR + col];
                bh[0] = __byte_perm(x0, x1, 0x5410); bl[0] = __byte_perm(x0, x1, 0x7632);
                bh[1] = __byte_perm(x2, x3, 0x5410); bl[1] = __byte_perm(x2, x3, 0x7632);
            }
#pragma unroll
            for (int mi = 0; mi < 4; mi++) {
                mma_bf16(acc[mi][ni], al[mi], bh);
                mma_bf16(acc[mi][ni], ah[mi], bl);
                mma_bf16(acc[mi][ni], ah[mi], bh);
            }
        }
        if (++bt == NSTAGE) bt = 0;
    }
    __syncthreads();
}

// EPI: 1 +bias, 2 gelu(+bias), 3 *scale+logw(per-z). SOUT: packed out.
template<int EPI, bool TRB, bool SOUT>
__global__ __launch_bounds__(256, 2)
void gemm_tc(const unsigned* __restrict__ A, const unsigned* __restrict__ B,
             const float* __restrict__ aux, float* __restrict__ C,
             unsigned* __restrict__ C2,
             int N, int K, int ldA, float scale,
             size_t sA, size_t sB, size_t sC, size_t sAux)
{
    extern __shared__ unsigned smu[];
    unsigned* As = smu;
    unsigned* Bs = smu + NSTAGE * A_BUF;
    const int bm = blockIdx.y * 128, bn = blockIdx.x * 128, z = blockIdx.z;

    float acc[4][4][4];
#pragma unroll
    for (int a = 0; a < 4; a++)
#pragma unroll
        for (int b = 0; b < 4; b++)
#pragma unroll
            for (int c = 0; c < 4; c++) acc[a][b][c] = 0.f;

    tc_core<TRB>(A + (size_t)z * sA, ldA, B + (size_t)z * sB, TRB ? K : N,
                 K, bm, bn, acc, As, Bs);

    const int tid = threadIdx.x, lane = tid & 31, warp = tid >> 5;
    const int g = lane >> 2, t4 = lane & 3;
    const int m0 = (warp >> 2) * 64, n0 = (warp & 3) * 32;
    const float* ax = aux + (size_t)z * sAux;
#pragma unroll
    for (int mi = 0; mi < 4; mi++) {
#pragma unroll
        for (int ni = 0; ni < 4; ni++) {
            int col = bn + n0 + ni * 8 + 2 * t4;
#pragma unroll
            for (int h = 0; h < 2; h++) {
                int row = bm + m0 + mi * 16 + g + h * 8;
                float v0 = acc[mi][ni][2 * h], v1 = acc[mi][ni][2 * h + 1];
                if (EPI == 1) { v0 += ax[col]; v1 += ax[col + 1]; }
                if (EPI == 2) { v0 = gelu_tanh(v0 + ax[col]); v1 = gelu_tanh(v1 + ax[col + 1]); }
                if (EPI == 3) { v0 = v0 * scale + ax[col]; v1 = v1 * scale + ax[col + 1]; }
                if (SOUT) {
                    *(uint2*)(C2 + (size_t)z * sC + (size_t)row * N + col) =
                        make_uint2(pack_b2(v0), pack_b2(v1));
                } else {
                    *(float2*)(C + (size_t)z * sC + (size_t)row * N + col) =
                        make_float2(v0, v1);
                }
            }
        }
    }
}

// ---------------- split-K GEMM for pooled = A @ V (fp32 partials) ------------
__global__ __launch_bounds__(256, 2)
void gemm_avk(const unsigned* __restrict__ Ss, const unsigned* __restrict__ Vs,
              float* __restrict__ Pt)
{
    extern __shared__ unsigned smu[];
    unsigned* As = smu;
    unsigned* Bs = smu + NSTAGE * A_BUF;
    const int bz = blockIdx.z;
    const int b = bz >> 3, kc = bz & (KSPLIT - 1);
    const int KC = NN_ / KSPLIT; // 512
    const unsigned* A  = Ss + (size_t)b * PP * NN_ + (size_t)kc * KC;
    const unsigned* Bm = Vs + (size_t)b * NN_ * DV_ + (size_t)kc * KC * DV_;
    const int bm = blockIdx.y * 128;

    float acc[4][4][4];
#pragma unroll
    for (int a = 0; a < 4; a++)
#pragma unroll
        for (int bb = 0; bb < 4; bb++)
#pragma unroll
            for (int c = 0; c < 4; c++) acc[a][bb][c] = 0.f;

    tc_core<false>(A, NN_, Bm, DV_, KC, bm, 0, acc, As, Bs);

    const int tid = threadIdx.x, lane = tid & 31, warp = tid >> 5;
    const int g = lane >> 2, t4 = lane & 3;
    const int m0 = (warp >> 2) * 64, n0 = (warp & 3) * 32;
    float* c0 = Pt + (size_t)bz * PP * DV_;
#pragma unroll
    for (int mi = 0; mi < 4; mi++)
#pragma unroll
        for (int ni = 0; ni < 4; ni++) {
            int col = n0 + ni * 8 + 2 * t4;
#pragma unroll
            for (int h = 0; h < 2; h++) {
                int row = bm + m0 + mi * 16 + g + h * 8;
                *(float2*)(c0 + (size_t)row * DV_ + col) =
                    make_float2(acc[mi][ni][2 * h], acc[mi][ni][2 * h + 1]);
            }
        }
}

__global__ __launch_bounds__(256)
void reduce_avk(const float* __restrict__ Pt, unsigned* __restrict__ pool2)
{
    const size_t total = (size_t)BB * PP * DV_;
    size_t i = (size_t)blockIdx.x * 256 + threadIdx.x;
    if (i >= total) return;
    size_t b = i / ((size_t)PP * DV_);
    size_t r = i - b * (size_t)PP * DV_;
    const float* p = Pt + b * KSPLIT * (size_t)PP * DV_ + r;
    float s = 0.f;
#pragma unroll
    for (int kc = 0; kc < KSPLIT; kc++) s += p[(size_t)kc * PP * DV_];
    pool2[i] = pack_b2(s);
}

// ---------------- softmax over 4096-wide rows, in-place on packed buffer -----
__global__ __launch_bounds__(256)
void softmax4096(unsigned* __restrict__ S2)
{
    unsigned* s = S2 + (size_t)blockIdx.x * NN_;
    const int t = threadIdx.x;
    const int w = t >> 5, lane = t & 31;
    __shared__ float red[8];

    float v[16];
    float mx = -INFINITY;
#pragma unroll
    for (int i = 0; i < 16; i++) {
        v[i] = unpack_b2(s[t + i * 256]);
        mx = fmaxf(mx, v[i]);
    }
    mx = warp_max(mx);
    if (lane == 0) red[w] = mx;
    __syncthreads();
    mx = red[0];
#pragma unroll
    for (int i = 1; i < 8; i++) mx = fmaxf(mx, red[i]);
    __syncthreads();

    float sum = 0.f;
#pragma unroll
    for (int i = 0; i < 16; i++) { v[i] = __expf(v[i] - mx); sum += v[i]; }
    sum = warp_sum(sum);
    if (lane == 0) red[w] = sum;
    __syncthreads();
    float tot = 0.f;
#pragma unroll
    for (int i = 0; i < 8; i++) tot += red[i];
    float inv = 1.0f / tot;
#pragma unroll
    for (int i = 0; i < 16; i++) s[t + i * 256] = pack_b2(v[i] * inv);
}

// ---------------- Q = LayerNorm(Q + dQ); emits fp32 + packed -----------------
__global__ __launch_bounds__(128)
void add_layernorm(float* __restrict__ Q, unsigned* __restrict__ Q2,
                   const float* __restrict__ dQ,
                   const float* __restrict__ g, const float* __restrict__ b)
{
    const int row = blockIdx.x, t = threadIdx.x;
    const size_t idx = (size_t)row * DK_ + t;
    const int w = t >> 5, lane = t & 31;
    __shared__ float sh[4];

    float x = Q[idx] + dQ[idx];
    float s = warp_sum(x);
    if (lane == 0) sh[w] = s;
    __syncthreads();
    float mean = (sh[0] + sh[1] + sh[2] + sh[3]) * (1.0f / DK_);
    float d = x - mean;
    __syncthreads();
    float s2 = warp_sum(d * d);
    if (lane == 0) sh[w] = s2;
    __syncthreads();
    float var = (sh[0] + sh[1] + sh[2] + sh[3]) * (1.0f / DK_);
    float y = d * rsqrtf(var + 1e-5f) * g[t] + b[t];
    Q[idx] = y;
    Q2[idx] = pack_b2(y);
}

// ---------------- prep kernels -----------------------------------------------
__global__ void prep_logw(const void* __restrict__ mask, const float* __restrict__ sw,
                          float* __restrict__ lw, int n)
{
    const unsigned int w0 = *(const unsigned int*)mask;
    const int mode = (w0 == 0x3F800000u) ? 2 : ((w0 == 1u) ? 1 : 0);
    int i = blockIdx.x * blockDim.x + threadIdx.x;
    if (i >= n) return;
    bool on;
    if (mode == 1)      on = ((const int*)mask)[i] != 0;
    else if (mode == 2) on = ((const float*)mask)[i] != 0.f;
    else                on = ((const unsigned char*)mask)[i] != 0;
    lw[i] = on ? logf(fmaxf(sw[i], 1e-8f)) : -INFINITY;
}

// One kernel packs all 10 weight matrices. blockIdx.y selects the segment.
__global__ void pack_all(const float* w0, const float* w1, const float* w2,
                         const float* w3, const float* w4, const float* w5,
                         const float* w6, const float* w7, const float* w8,
                         const float* w9, unsigned* __restrict__ ws)
{
    const unsigned offs[10] = { WOFF_KW1, WOFF_KW2, WOFF_KW3, WOFF_VW1, WOFF_VW2,
                                WOFF_VW3, WOFF_RW1, WOFF_RW2, WOFF_FW1, WOFF_FW2 };
    const unsigned cnts[10] = { 65536u, 262144u, 65536u, 98304u, 262144u,
                                65536u, 65536u, 131072u, 65536u, 65536u };
    const int seg = blockIdx.y;
    const float* src;
    switch (seg) {
        case 0: src = w0; break; case 1: src = w1; break; case 2: src = w2; break;
        case 3: src = w3; break; case 4: src = w4; break; case 5: src = w5; break;
        case 6: src = w6; break; case 7: src = w7; break; case 8: src = w8; break;
        default: src = w9; break;
    }
    unsigned* dst = ws + offs[seg];
    const unsigned n = cnts[seg];
    for (unsigned i = blockIdx.x * blockDim.x + threadIdx.x; i < n;
         i += gridDim.x * blockDim.x)
        dst[i] = pack_b2(src[i]);
}

__global__ void concat_xu(const float* __restrict__ x, const float* __restrict__ u,
                          unsigned* __restrict__ xu2)
{
    const size_t total = (size_t)TOK * (DX_ + DU_);
    for (size_t i = (size_t)blockIdx.x * blockDim.x + threadIdx.x; i < total;
         i += (size_t)gridDim.x * blockDim.x) {
        size_t tkn = i / (DX_ + DU_);
        int c = (int)(i - tkn * (DX_ + DU_));
        float v = (c < DX_) ? x[tkn * DX_ + c] : u[tkn * DU_ + (c - DX_)];
        xu2[i] = pack_b2(v);
    }
}

__global__ void bcast_q(const float* __restrict__ qt, float* __restrict__ Q,
                        unsigned* __restrict__ Q2)
{
    const size_t total = (size_t)BPQ * DK_;
    const size_t per = (size_t)PP * DK_;
    for (size_t i = (size_t)blockIdx.x * blockDim.x + threadIdx.x; i < total;
         i += (size_t)gridDim.x * blockDim.x) {
        float v = qt[i % per];
        Q[i] = v;
        Q2[i] = pack_b2(v);
    }
}

// ---------------- host launcher ----------------------------------------------
extern "C" void kernel_launch(void* const* d_in, const int* in_sizes, int n_in,
                              void* d_out, int out_size)
{
    const float* x_enc = (const float*)d_in[0];
    const float* u     = (const float*)d_in[1];
    const void*  mask  = d_in[2];
    const float* sw    = (const float*)d_in[3];
    const float* k_w1 = (const float*)d_in[4];  const float* k_b1 = (const float*)d_in[5];
    const float* k_w2 = (const float*)d_in[6];  const float* k_b2 = (const float*)d_in[7];
    const float* k_w3 = (const float*)d_in[8];  const float* k_b3 = (const float*)d_in[9];
    const float* v_w1 = (const float*)d_in[10]; const float* v_b1 = (const float*)d_in[11];
    const float* v_w2 = (const float*)d_in[12]; const float* v_b2 = (const float*)d_in[13];
    const float* v_w3 = (const float*)d_in[14]; const float* v_b3 = (const float*)d_in[15];
    const float* qtok = (const float*)d_in[16];
    const float* rho_w1 = (const float*)d_in[17]; const float* rho_b1 = (const float*)d_in[18];
    const float* rho_w2 = (const float*)d_in[19]; const float* rho_b2 = (const float*)d_in[20];
    const float* ref_w1 = (const float*)d_in[21]; const float* ref_b1 = (const float*)d_in[22];
    const float* ref_w2 = (const float*)d_in[23]; const float* ref_b2 = (const float*)d_in[24];
    const float* ln_g = (const float*)d_in[25];   const float* ln_b = (const float*)d_in[26];
    float* out = (float*)d_out;

    char* arena;
    cudaGetSymbolAddress((void**)&arena, g_arena);
    unsigned* xu2   = (unsigned*)(arena + OFF_XU2);
    unsigned* h1s   = (unsigned*)(arena + OFF_H1S);
    unsigned* h2s   = (unsigned*)(arena + OFF_H2S);
    unsigned* Ss    = (unsigned*)(arena + OFF_SS);     // aliases h2s
    unsigned* Ks    = (unsigned*)(arena + OFF_KS);
    unsigned* Vs    = (unsigned*)(arena + OFF_VS);
    float*    pt    = (float*)(arena + OFF_PT);
    unsigned* ws    = (unsigned*)(arena + OFF_WS);
    float*    Q     = (float*)(arena + OFF_Q);
    unsigned* Qs    = (unsigned*)(arena + OFF_QS);
    unsigned* pools = (unsigned*)(arena + OFF_POOLS);
    float*    dQ    = (float*)(arena + OFF_DQ);
    float*    lw    = (float*)(arena + OFF_LW);

    cudaFuncSetAttribute(gemm_tc<2,false,true>,  cudaFuncAttributeMaxDynamicSharedMemorySize, SMEM_NN);
    cudaFuncSetAttribute(gemm_tc<1,false,true>,  cudaFuncAttributeMaxDynamicSharedMemorySize, SMEM_NN);
    cudaFuncSetAttribute(gemm_tc<1,false,false>, cudaFuncAttributeMaxDynamicSharedMemorySize, SMEM_NN);
    cudaFuncSetAttribute(gemm_tc<3,true,true>,   cudaFuncAttributeMaxDynamicSharedMemorySize, SMEM_TRB);
    cudaFuncSetAttribute(gemm_avk,               cudaFuncAttributeMaxDynamicSharedMemorySize, SMEM_NN);

    const float scale = 0.08838834764831843f; // 1/sqrt(128)

    // prep + one-shot packs
    prep_logw<<<(TOK + 255) / 256, 256>>>(mask, sw, lw, TOK);
    concat_xu<<<4096, 256>>>(x_enc, u, xu2);
    bcast_q<<<1024, 256>>>(qtok, Q, Qs);
    pack_all<<<dim3(192, 10), 256>>>(k_w1, k_w2, k_w3, v_w1, v_w2, v_w3,
                                     rho_w1, rho_w2, ref_w1, ref_w2, ws);

    // K = mlp3(x_enc)  — layer 1 reads the x-half of xu2 (ldA = 192)
    gemm_tc<2,false,true><<<dim3(HH/128, TOK/128, 1), 256, SMEM_NN>>>(
        xu2, ws + WOFF_KW1, k_b1, nullptr, h1s, HH, DX_, DX_+DU_, 0.f, 0,0,0,0);
    gemm_tc<2,false,true><<<dim3(HH/128, TOK/128, 1), 256, SMEM_NN>>>(
        h1s, ws + WOFF_KW2, k_b2, nullptr, h2s, HH, HH, HH, 0.f, 0,0,0,0);
    gemm_tc<1,false,true><<<dim3(DK_/128, TOK/128, 1), 256, SMEM_NN>>>(
        h2s, ws + WOFF_KW3, k_b3, nullptr, Ks, DK_, HH, HH, 0.f, 0,0,0,0);

    // V = mlp3([x_enc|u])
    gemm_tc<2,false,true><<<dim3(HH/128, TOK/128, 1), 256, SMEM_NN>>>(
        xu2, ws + WOFF_VW1, v_b1, nullptr, h1s, HH, DX_+DU_, DX_+DU_, 0.f, 0,0,0,0);
    gemm_tc<2,false,true><<<dim3(HH/128, TOK/128, 1), 256, SMEM_NN>>>(
        h1s, ws + WOFF_VW2, v_b2, nullptr, h2s, HH, HH, HH, 0.f, 0,0,0,0);
    gemm_tc<1,false,true><<<dim3(DV_/128, TOK/128, 1), 256, SMEM_NN>>>(
        h2s, ws + WOFF_VW3, v_b3, nullptr, Vs, DV_, HH, HH, 0.f, 0,0,0,0);

    // attention + refinement (3 iterations).  Ss aliases h2s (dead after V-MLP).
    for (int iter = 0; iter < 3; iter++) {
        gemm_tc<3,true,true><<<dim3(NN_/128, PP/128, BB), 256, SMEM_TRB>>>(
            Qs, Ks, lw, nullptr, Ss, NN_, DK_, DK_, scale,
            (size_t)PP*DK_, (size_t)NN_*DK_, (size_t)PP*NN_, (size_t)NN_);
        softmax4096<<<BB*PP, 256>>>(Ss);
        gemm_avk<<<dim3(1, PP/128, BB*KSPLIT), 256, SMEM_NN>>>(Ss, Vs, pt);
        reduce_avk<<<(BB*PP*DV_ + 255)/256, 256>>>(pt, pools);
        if (iter < 2) {
            gemm_tc<2,false,true><<<dim3(HH/128, BPQ/128, 1), 256, SMEM_NN>>>(
                pools, ws + WOFF_FW1, ref_b1, nullptr, h1s, HH, DV_, DV_, 0.f, 0,0,0,0);
            gemm_tc<1,false,false><<<dim3(DK_/128, BPQ/128, 1), 256, SMEM_NN>>>(
                h1s, ws + WOFF_FW2, ref_b2, dQ, nullptr, DK_, HH, HH, 0.f, 0,0,0,0);
            add_layernorm<<<BPQ, 128>>>(Q, Qs, dQ, ln_g, ln_b);
        }
    }

    // out = mlp2(pooled)
    gemm_tc<2,false,true><<<dim3(HH/128, BPQ/128, 1), 256, SMEM_NN>>>(
        pools, ws + WOFF_RW1, rho_b1, nullptr, h1s, HH, DV_, DV_, 0.f, 0,0,0,0);
    gemm_tc<1,false,false><<<dim3(DOUT_/128, BPQ/128, 1), 256, SMEM_NN>>>(
        h1s, ws + WOFF_RW2, rho_b2, out, nullptr, DOUT_, HH, HH, 0.f, 0,0,0,0);

    (void)in_sizes; (void)n_in; (void)out_size;
}

// round 17
// speedup vs baseline: 1.0257x; 1.0257x over previous
#include <cuda_runtime.h>
#include <cuda_bf16.h>
#include <math.h>
#include <cstdint>
#include <cstddef>

typedef __nv_bfloat16 bf16;

// Problem constants
#define BB   32
#define NN_  4096
#define PP   256
#define DX_  128
#define DU_  64
#define DK_  128
#define DV_  128
#define DOUT_ 256
#define HH   512
#define TOK  (BB*NN_)   // 131072
#define BPQ  (BB*PP)    // 8192
#define KSPLIT 8

// ---------------- single arena (packed b2 = 4 B/elem) ------------------------
#define OFF_XU2   0ull
#define OFF_H1S   100663296ull
#define OFF_H2S   369098752ull
#define OFF_SS    OFF_H2S            /* aliases h2s (dead after V-MLP) */
#define OFF_KS    637534208ull
#define OFF_VS    704643072ull
#define OFF_PT    771751936ull
#define OFF_WS    805306368ull
#define OFF_Q     809893888ull
#define OFF_QS    814088192ull
#define OFF_POOLS 818282496ull
#define OFF_DQ    822476800ull
#define OFF_LW    826671104ull
#define ARENA_BYTES 827195392ull

__device__ __align__(1024) char g_arena[ARENA_BYTES];

// weight plane offsets (words) inside ws
#define WOFF_KW1 0u
#define WOFF_KW2 65536u
#define WOFF_KW3 327680u
#define WOFF_VW1 393216u
#define WOFF_VW2 491520u
#define WOFF_VW3 753664u
#define WOFF_RW1 819200u
#define WOFF_RW2 884736u
#define WOFF_FW1 1015808u
#define WOFF_FW2 1081344u

// ---------------- helpers ----------------------------------------------------
// gelu(tanh approx) via expf: gelu = x * t/(t+1), t = exp(2*0.79788456*(x+0.044715x^3))
__device__ __forceinline__ float gelu_tanh(float x) {
    float u = 1.5957691216057308f * (x + 0.044715f * x * x * x);
    u = fminf(fmaxf(u, -30.f), 30.f);
    float t = __expf(u);
    return x * __fdividef(t, t + 1.f);
}
__device__ __forceinline__ float warp_sum(float v) {
#pragma unroll
    for (int o = 16; o > 0; o >>= 1) v += __shfl_xor_sync(0xffffffffu, v, o);
    return v;
}
__device__ __forceinline__ float warp_max(float v) {
#pragma unroll
    for (int o = 16; o > 0; o >>= 1) v = fmaxf(v, __shfl_xor_sync(0xffffffffu, v, o));
    return v;
}
// pack x as (bf16 hi | bf16 lo<<16); x ~= hi + lo. Guards inf/nan (lo = 0).
__device__ __forceinline__ unsigned pack_b2(float x) {
    bf16 hb = __float2bfloat16(x);
    float hf = __bfloat162float(hb);
    float r = x - hf;
    if (!(fabsf(hf) <= 3.38e38f)) r = 0.f;
    bf16 lb = __float2bfloat16(r);
    return (unsigned)__bfloat16_as_ushort(hb) |
           ((unsigned)__bfloat16_as_ushort(lb) << 16);
}
__device__ __forceinline__ float unpack_b2(unsigned w) {
    return __bfloat162float(__ushort_as_bfloat16((unsigned short)(w & 0xFFFFu)))
         + __bfloat162float(__ushort_as_bfloat16((unsigned short)(w >> 16)));
}
__device__ __forceinline__ void mma_bf16(float d[4], const unsigned a[4], const unsigned b[2]) {
    asm volatile(
        "mma.sync.aligned.m16n8k16.row.col.f32.bf16.bf16.f32 "
        "{%0,%1,%2,%3}, {%4,%5,%6,%7}, {%8,%9}, {%0,%1,%2,%3};\n"
        : "+f"(d[0]), "+f"(d[1]), "+f"(d[2]), "+f"(d[3])
        : "r"(a[0]), "r"(a[1]), "r"(a[2]), "r"(a[3]), "r"(b[0]), "r"(b[1]));
}
__device__ __forceinline__ unsigned smem_u32(const void* p) {
    return (unsigned)__cvta_generic_to_shared(p);
}
__device__ __forceinline__ void cp16(unsigned dst, const void* src) {
    asm volatile("cp.async.cg.shared.global [%0], [%1], 16;\n" :: "r"(dst), "l"(src));
}

// smem geometry (units = uint32 words) — r14/r6-exact (2-stage)
#define A_STR 24
#define A_BUF (128*A_STR)            // 3072
template<bool TRB> struct BCfg;
template<> struct BCfg<false> { static constexpr int STR = 132; static constexpr int BUF = 16*132;  };
template<> struct BCfg<true>  { static constexpr int STR = 24;  static constexpr int BUF = 128*24;  };
#define SMEM_NN  ((2*A_BUF + 2*BCfg<false>::BUF) * 4)  // 41472 B
#define SMEM_TRB ((2*A_BUF + 2*BCfg<true>::BUF)  * 4)  // 49152 B

// =============================================================================
// 3xBF16 tensor-core GEMM core on packed (hi|lo) uint32 operands (r14-exact).
// 128x128 tile, BK=16, 256 threads, warps 2(m) x 4(n), 64x32 per warp.
// =============================================================================
template<bool TRB>
__device__ __forceinline__ void tc_core(
    const unsigned* __restrict__ Ag, int lda,
    const unsigned* __restrict__ Bg, int ldb,
    int K, int bm, int bn, float (&acc)[4][4][4],
    unsigned* As, unsigned* Bs)
{
    const int tid = threadIdx.x, lane = tid & 31;
    const int g = lane >> 2, t4 = lane & 3;
    const int warp = tid >> 5;
    const int m0 = (warp >> 2) * 64, n0 = (warp & 3) * 32;
    constexpr int BSTR = BCfg<TRB>::STR;
    constexpr int BBUF = BCfg<TRB>::BUF;

    auto issue = [&](int k0, int buf) {
#pragma unroll
        for (int i = 0; i < 2; i++) {
            int idx = tid + i * 256;
            int r = idx >> 2, q = (idx & 3) * 4;
            cp16(smem_u32(As + buf * A_BUF + r * A_STR + q),
                 Ag + (size_t)(bm + r) * lda + k0 + q);
        }
#pragma unroll
        for (int i = 0; i < 2; i++) {
            int idx = tid + i * 256;
            if (TRB) {
                int r = idx >> 2, q = (idx & 3) * 4;
                cp16(smem_u32(Bs + buf * BBUF + r * BSTR + q),
                     Bg + (size_t)(bn + r) * ldb + k0 + q);
            } else {
                int r = idx >> 5, q = (idx & 31) * 4;
                cp16(smem_u32(Bs + buf * BBUF + r * BSTR + q),
                     Bg + (size_t)(k0 + r) * ldb + bn + q);
            }
        }
        asm volatile("cp.async.commit_group;\n");
    };

    const int nt = K >> 4;
    issue(0, 0);
    for (int t = 0; t < nt; t++) {
        const int buf = t & 1;
        if (t + 1 < nt) { issue((t + 1) << 4, buf ^ 1); asm volatile("cp.async.wait_group 1;\n"); }
        else            { asm volatile("cp.async.wait_group 0;\n"); }
        __syncthreads();
        const unsigned* Ab = As + buf * A_BUF;
        const unsigned* Bb = Bs + buf * BBUF;

        unsigned ah[4][4], al[4][4];
#pragma unroll
        for (int mi = 0; mi < 4; mi++) {
            int mr = m0 + mi * 16;
            uint2 w0 = *(const uint2*)&Ab[(mr + g    ) * A_STR + 2 * t4    ];
            uint2 w1 = *(const uint2*)&Ab[(mr + g + 8) * A_STR + 2 * t4    ];
            uint2 w2 = *(const uint2*)&Ab[(mr + g    ) * A_STR + 2 * t4 + 8];
            uint2 w3 = *(const uint2*)&Ab[(mr + g + 8) * A_STR + 2 * t4 + 8];
            ah[mi][0] = __byte_perm(w0.x, w0.y, 0x5410); al[mi][0] = __byte_perm(w0.x, w0.y, 0x7632);
            ah[mi][1] = __byte_perm(w1.x, w1.y, 0x5410); al[mi][1] = __byte_perm(w1.x, w1.y, 0x7632);
            ah[mi][2] = __byte_perm(w2.x, w2.y, 0x5410); al[mi][2] = __byte_perm(w2.x, w2.y, 0x7632);
            ah[mi][3] = __byte_perm(w3.x, w3.y, 0x5410); al[mi][3] = __byte_perm(w3.x, w3.y, 0x7632);
        }
#pragma unroll
        for (int ni = 0; ni < 4; ni++) {
            unsigned bh[2], bl[2];
            if (TRB) {
                int nr = n0 + ni * 8 + g;
                uint2 v0 = *(const uint2*)&Bb[nr * BSTR + 2 * t4    ];
                uint2 v1 = *(const uint2*)&Bb[nr * BSTR + 2 * t4 + 8];
                bh[0] = __byte_perm(v0.x, v0.y, 0x5410); bl[0] = __byte_perm(v0.x, v0.y, 0x7632);
                bh[1] = __byte_perm(v1.x, v1.y, 0x5410); bl[1] = __byte_perm(v1.x, v1.y, 0x7632);
            } else {
                int col = n0 + ni * 8 + g;
                unsigned x0 = Bb[(2 * t4    ) * BSTR + col];
                unsigned x1 = Bb[(2 * t4 + 1) * BSTR + col];
                unsigned x2 = Bb[(2 * t4 + 8) * BSTR + col];
                unsigned x3 = Bb[(2 * t4 + 9) * BSTR + col];
                bh[0] = __byte_perm(x0, x1, 0x5410); bl[0] = __byte_perm(x0, x1, 0x7632);
                bh[1] = __byte_perm(x2, x3, 0x5410); bl[1] = __byte_perm(x2, x3, 0x7632);
            }
#pragma unroll
            for (int mi = 0; mi < 4; mi++) {
                mma_bf16(acc[mi][ni], al[mi], bh);
                mma_bf16(acc[mi][ni], ah[mi], bl);
                mma_bf16(acc[mi][ni], ah[mi], bh);
            }
        }
        __syncthreads();
    }
}

// EPI: 1 +bias, 2 gelu(+bias), 3 *scale+logw(per-z). SOUT: packed out.
template<int EPI, bool TRB, bool SOUT>
__global__ __launch_bounds__(256, 2)
void gemm_tc(const unsigned* __restrict__ A, const unsigned* __restrict__ B,
             const float* __restrict__ aux, float* __restrict__ C,
             unsigned* __restrict__ C2,
             int N, int K, int ldA, float scale,
             size_t sA, size_t sB, size_t sC, size_t sAux)
{
    extern __shared__ unsigned smu[];
    unsigned* As = smu;
    unsigned* Bs = smu + 2 * A_BUF;
    const int bm = blockIdx.y * 128, bn = blockIdx.x * 128, z = blockIdx.z;

    float acc[4][4][4];
#pragma unroll
    for (int a = 0; a < 4; a++)
#pragma unroll
        for (int b = 0; b < 4; b++)
#pragma unroll
            for (int c = 0; c < 4; c++) acc[a][b][c] = 0.f;

    tc_core<TRB>(A + (size_t)z * sA, ldA, B + (size_t)z * sB, TRB ? K : N,
                 K, bm, bn, acc, As, Bs);

    const int tid = threadIdx.x, lane = tid & 31, warp = tid >> 5;
    const int g = lane >> 2, t4 = lane & 3;
    const int m0 = (warp >> 2) * 64, n0 = (warp & 3) * 32;
    const float* ax = aux + (size_t)z * sAux;
#pragma unroll
    for (int mi = 0; mi < 4; mi++) {
#pragma unroll
        for (int ni = 0; ni < 4; ni++) {
            int col = bn + n0 + ni * 8 + 2 * t4;
#pragma unroll
            for (int h = 0; h < 2; h++) {
                int row = bm + m0 + mi * 16 + g + h * 8;
                float v0 = acc[mi][ni][2 * h], v1 = acc[mi][ni][2 * h + 1];
                if (EPI == 1) { v0 += ax[col]; v1 += ax[col + 1]; }
                if (EPI == 2) { v0 = gelu_tanh(v0 + ax[col]); v1 = gelu_tanh(v1 + ax[col + 1]); }
                if (EPI == 3) { v0 = v0 * scale + ax[col]; v1 = v1 * scale + ax[col + 1]; }
                if (SOUT) {
                    *(uint2*)(C2 + (size_t)z * sC + (size_t)row * N + col) =
                        make_uint2(pack_b2(v0), pack_b2(v1));
                } else {
                    *(float2*)(C + (size_t)z * sC + (size_t)row * N + col) =
                        make_float2(v0, v1);
                }
            }
        }
    }
}

// ---------------- split-K GEMM for pooled = A @ V (fp32 partials) ------------
__global__ __launch_bounds__(256, 2)
void gemm_avk(const unsigned* __restrict__ Ss, const unsigned* __restrict__ Vs,
              float* __restrict__ Pt)
{
    extern __shared__ unsigned smu[];
    unsigned* As = smu;
    unsigned* Bs = smu + 2 * A_BUF;
    const int bz = blockIdx.z;
    const int b = bz >> 3, kc = bz & (KSPLIT - 1);
    const int KC = NN_ / KSPLIT; // 512
    const unsigned* A  = Ss + (size_t)b * PP * NN_ + (size_t)kc * KC;
    const unsigned* Bm = Vs + (size_t)b * NN_ * DV_ + (size_t)kc * KC * DV_;
    const int bm = blockIdx.y * 128;

    float acc[4][4][4];
#pragma unroll
    for (int a = 0; a < 4; a++)
#pragma unroll
        for (int bb = 0; bb < 4; bb++)
#pragma unroll
            for (int c = 0; c < 4; c++) acc[a][bb][c] = 0.f;

    tc_core<false>(A, NN_, Bm, DV_, KC, bm, 0, acc, As, Bs);

    const int tid = threadIdx.x, lane = tid & 31, warp = tid >> 5;
    const int g = lane >> 2, t4 = lane & 3;
    const int m0 = (warp >> 2) * 64, n0 = (warp & 3) * 32;
    float* c0 = Pt + (size_t)bz * PP * DV_;
#pragma unroll
    for (int mi = 0; mi < 4; mi++)
#pragma unroll
        for (int ni = 0; ni < 4; ni++) {
            int col = n0 + ni * 8 + 2 * t4;
#pragma unroll
            for (int h = 0; h < 2; h++) {
                int row = bm + m0 + mi * 16 + g + h * 8;
                *(float2*)(c0 + (size_t)row * DV_ + col) =
                    make_float2(acc[mi][ni][2 * h], acc[mi][ni][2 * h + 1]);
            }
        }
}

__global__ __launch_bounds__(256)
void reduce_avk(const float* __restrict__ Pt, unsigned* __restrict__ pool2)
{
    const size_t total = (size_t)BB * PP * DV_;
    size_t i = (size_t)blockIdx.x * 256 + threadIdx.x;
    if (i >= total) return;
    size_t b = i / ((size_t)PP * DV_);
    size_t r = i - b * (size_t)PP * DV_;
    const float* p = Pt + b * KSPLIT * (size_t)PP * DV_ + r;
    float s = 0.f;
#pragma unroll
    for (int kc = 0; kc < KSPLIT; kc++) s += p[(size_t)kc * PP * DV_];
    pool2[i] = pack_b2(s);
}

// ---------------- softmax over 4096-wide rows, in-place, uint4-vectorized ----
__global__ __launch_bounds__(256)
void softmax4096(unsigned* __restrict__ S2)
{
    uint4* s = (uint4*)(S2 + (size_t)blockIdx.x * NN_);  // 1024 uint4 per row
    const int t = threadIdx.x;
    const int w = t >> 5, lane = t & 31;
    __shared__ float red[8];

    uint4 pk[4];
    float v[16];
    float mx = -INFINITY;
#pragma unroll
    for (int i = 0; i < 4; i++) {
        pk[i] = s[t + i * 256];
        v[4*i]   = unpack_b2(pk[i].x);
        v[4*i+1] = unpack_b2(pk[i].y);
        v[4*i+2] = unpack_b2(pk[i].z);
        v[4*i+3] = unpack_b2(pk[i].w);
        mx = fmaxf(mx, fmaxf(fmaxf(v[4*i], v[4*i+1]), fmaxf(v[4*i+2], v[4*i+3])));
    }
    mx = warp_max(mx);
    if (lane == 0) red[w] = mx;
    __syncthreads();
    mx = red[0];
#pragma unroll
    for (int i = 1; i < 8; i++) mx = fmaxf(mx, red[i]);
    __syncthreads();

    float sum = 0.f;
#pragma unroll
    for (int i = 0; i < 16; i++) { v[i] = __expf(v[i] - mx); sum += v[i]; }
    sum = warp_sum(sum);
    if (lane == 0) red[w] = sum;
    __syncthreads();
    float tot = 0.f;
#pragma unroll
    for (int i = 0; i < 8; i++) tot += red[i];
    float inv = 1.0f / tot;
#pragma unroll
    for (int i = 0; i < 4; i++) {
        uint4 o;
        o.x = pack_b2(v[4*i]   * inv);
        o.y = pack_b2(v[4*i+1] * inv);
        o.z = pack_b2(v[4*i+2] * inv);
        o.w = pack_b2(v[4*i+3] * inv);
        s[t + i * 256] = o;
    }
}

// ---------------- Q = LayerNorm(Q + dQ); emits fp32 + packed -----------------
__global__ __launch_bounds__(128)
void add_layernorm(float* __restrict__ Q, unsigned* __restrict__ Q2,
                   const float* __restrict__ dQ,
                   const float* __restrict__ g, const float* __restrict__ b)
{
    const int row = blockIdx.x, t = threadIdx.x;
    const size_t idx = (size_t)row * DK_ + t;
    const int w = t >> 5, lane = t & 31;
    __shared__ float sh[4];

    float x = Q[idx] + dQ[idx];
    float s = warp_sum(x);
    if (lane == 0) sh[w] = s;
    __syncthreads();
    float mean = (sh[0] + sh[1] + sh[2] + sh[3]) * (1.0f / DK_);
    float d = x - mean;
    __syncthreads();
    float s2 = warp_sum(d * d);
    if (lane == 0) sh[w] = s2;
    __syncthreads();
    float var = (sh[0] + sh[1] + sh[2] + sh[3]) * (1.0f / DK_);
    float y = d * rsqrtf(var + 1e-5f) * g[t] + b[t];
    Q[idx] = y;
    Q2[idx] = pack_b2(y);
}

// ---------------- prep kernels -----------------------------------------------
__global__ void prep_logw(const void* __restrict__ mask, const float* __restrict__ sw,
                          float* __restrict__ lw, int n)
{
    const unsigned int w0 = *(const unsigned int*)mask;
    const int mode = (w0 == 0x3F800000u) ? 2 : ((w0 == 1u) ? 1 : 0);
    int i = blockIdx.x * blockDim.x + threadIdx.x;
    if (i >= n) return;
    bool on;
    if (mode == 1)      on = ((const int*)mask)[i] != 0;
    else if (mode == 2) on = ((const float*)mask)[i] != 0.f;
    else                on = ((const unsigned char*)mask)[i] != 0;
    lw[i] = on ? logf(fmaxf(sw[i], 1e-8f)) : -INFINITY;
}

// One kernel packs all 10 weight matrices. blockIdx.y selects the segment.
__global__ void pack_all(const float* w0, const float* w1, const float* w2,
                         const float* w3, const float* w4, const float* w5,
                         const float* w6, const float* w7, const float* w8,
                         const float* w9, unsigned* __restrict__ ws)
{
    const unsigned offs[10] = { WOFF_KW1, WOFF_KW2, WOFF_KW3, WOFF_VW1, WOFF_VW2,
                                WOFF_VW3, WOFF_RW1, WOFF_RW2, WOFF_FW1, WOFF_FW2 };
    const unsigned cnts[10] = { 65536u, 262144u, 65536u, 98304u, 262144u,
                                65536u, 65536u, 131072u, 65536u, 65536u };
    const int seg = blockIdx.y;
    const float* src;
    switch (seg) {
        case 0: src = w0; break; case 1: src = w1; break; case 2: src = w2; break;
        case 3: src = w3; break; case 4: src = w4; break; case 5: src = w5; break;
        case 6: src = w6; break; case 7: src = w7; break; case 8: src = w8; break;
        default: src = w9; break;
    }
    unsigned* dst = ws + offs[seg];
    const unsigned n = cnts[seg];
    for (unsigned i = blockIdx.x * blockDim.x + threadIdx.x; i < n;
         i += gridDim.x * blockDim.x)
        dst[i] = pack_b2(src[i]);
}

__global__ void concat_xu(const float* __restrict__ x, const float* __restrict__ u,
                          unsigned* __restrict__ xu2)
{
    const size_t total = (size_t)TOK * (DX_ + DU_);
    for (size_t i = (size_t)blockIdx.x * blockDim.x + threadIdx.x; i < total;
         i += (size_t)gridDim.x * blockDim.x) {
        size_t tkn = i / (DX_ + DU_);
        int c = (int)(i - tkn * (DX_ + DU_));
        float v = (c < DX_) ? x[tkn * DX_ + c] : u[tkn * DU_ + (c - DX_)];
        xu2[i] = pack_b2(v);
    }
}

__global__ void bcast_q(const float* __restrict__ qt, float* __restrict__ Q,
                        unsigned* __restrict__ Q2)
{
    const size_t total = (size_t)BPQ * DK_;
    const size_t per = (size_t)PP * DK_;
    for (size_t i = (size_t)blockIdx.x * blockDim.x + threadIdx.x; i < total;
         i += (size_t)gridDim.x * blockDim.x) {
        float v = qt[i % per];
        Q[i] = v;
        Q2[i] = pack_b2(v);
    }
}

// ---------------- host launcher ----------------------------------------------
extern "C" void kernel_launch(void* const* d_in, const int* in_sizes, int n_in,
                              void* d_out, int out_size)
{
    const float* x_enc = (const float*)d_in[0];
    const float* u     = (const float*)d_in[1];
    const void*  mask  = d_in[2];
    const float* sw    = (const float*)d_in[3];
    const float* k_w1 = (const float*)d_in[4];  const float* k_b1 = (const float*)d_in[5];
    const float* k_w2 = (const float*)d_in[6];  const float* k_b2 = (const float*)d_in[7];
    const float* k_w3 = (const float*)d_in[8];  const float* k_b3 = (const float*)d_in[9];
    const float* v_w1 = (const float*)d_in[10]; const float* v_b1 = (const float*)d_in[11];
    const float* v_w2 = (const float*)d_in[12]; const float* v_b2 = (const float*)d_in[13];
    const float* v_w3 = (const float*)d_in[14]; const float* v_b3 = (const float*)d_in[15];
    const float* qtok = (const float*)d_in[16];
    const float* rho_w1 = (const float*)d_in[17]; const float* rho_b1 = (const float*)d_in[18];
    const float* rho_w2 = (const float*)d_in[19]; const float* rho_b2 = (const float*)d_in[20];
    const float* ref_w1 = (const float*)d_in[21]; const float* ref_b1 = (const float*)d_in[22];
    const float* ref_w2 = (const float*)d_in[23]; const float* ref_b2 = (const float*)d_in[24];
    const float* ln_g = (const float*)d_in[25];   const float* ln_b = (const float*)d_in[26];
    float* out = (float*)d_out;

    char* arena;
    cudaGetSymbolAddress((void**)&arena, g_arena);
    unsigned* xu2   = (unsigned*)(arena + OFF_XU2);
    unsigned* h1s   = (unsigned*)(arena + OFF_H1S);
    unsigned* h2s   = (unsigned*)(arena + OFF_H2S);
    unsigned* Ss    = (unsigned*)(arena + OFF_SS);     // aliases h2s
    unsigned* Ks    = (unsigned*)(arena + OFF_KS);
    unsigned* Vs    = (unsigned*)(arena + OFF_VS);
    float*    pt    = (float*)(arena + OFF_PT);
    unsigned* ws    = (unsigned*)(arena + OFF_WS);
    float*    Q     = (float*)(arena + OFF_Q);
    unsigned* Qs    = (unsigned*)(arena + OFF_QS);
    unsigned* pools = (unsigned*)(arena + OFF_POOLS);
    float*    dQ    = (float*)(arena + OFF_DQ);
    float*    lw    = (float*)(arena + OFF_LW);

    cudaFuncSetAttribute(gemm_tc<2,false,true>,  cudaFuncAttributeMaxDynamicSharedMemorySize, SMEM_NN);
    cudaFuncSetAttribute(gemm_tc<1,false,true>,  cudaFuncAttributeMaxDynamicSharedMemorySize, SMEM_NN);
    cudaFuncSetAttribute(gemm_tc<1,false,false>, cudaFuncAttributeMaxDynamicSharedMemorySize, SMEM_NN);
    cudaFuncSetAttribute(gemm_tc<3,true,true>,   cudaFuncAttributeMaxDynamicSharedMemorySize, SMEM_TRB);
    cudaFuncSetAttribute(gemm_avk,               cudaFuncAttributeMaxDynamicSharedMemorySize, SMEM_NN);

    const float scale = 0.08838834764831843f; // 1/sqrt(128)

    // prep + one-shot packs
    prep_logw<<<(TOK + 255) / 256, 256>>>(mask, sw, lw, TOK);
    concat_xu<<<4096, 256>>>(x_enc, u, xu2);
    bcast_q<<<1024, 256>>>(qtok, Q, Qs);
    pack_all<<<dim3(192, 10), 256>>>(k_w1, k_w2, k_w3, v_w1, v_w2, v_w3,
                                     rho_w1, rho_w2, ref_w1, ref_w2, ws);

    // K = mlp3(x_enc)  — layer 1 reads the x-half of xu2 (ldA = 192)
    gemm_tc<2,false,true><<<dim3(HH/128, TOK/128, 1), 256, SMEM_NN>>>(
        xu2, ws + WOFF_KW1, k_b1, nullptr, h1s, HH, DX_, DX_+DU_, 0.f, 0,0,0,0);
    gemm_tc<2,false,true><<<dim3(HH/128, TOK/128, 1), 256, SMEM_NN>>>(
        h1s, ws + WOFF_KW2, k_b2, nullptr, h2s, HH, HH, HH, 0.f, 0,0,0,0);
    gemm_tc<1,false,true><<<dim3(DK_/128, TOK/128, 1), 256, SMEM_NN>>>(
        h2s, ws + WOFF_KW3, k_b3, nullptr, Ks, DK_, HH, HH, 0.f, 0,0,0,0);

    // V = mlp3([x_enc|u])
    gemm_tc<2,false,true><<<dim3(HH/128, TOK/128, 1), 256, SMEM_NN>>>(
        xu2, ws + WOFF_VW1, v_b1, nullptr, h1s, HH, DX_+DU_, DX_+DU_, 0.f, 0,0,0,0);
    gemm_tc<2,false,true><<<dim3(HH/128, TOK/128, 1), 256, SMEM_NN>>>(
        h1s, ws + WOFF_VW2, v_b2, nullptr, h2s, HH, HH, HH, 0.f, 0,0,0,0);
    gemm_tc<1,false,true><<<dim3(DV_/128, TOK/128, 1), 256, SMEM_NN>>>(
        h2s, ws + WOFF_VW3, v_b3, nullptr, Vs, DV_, HH, HH, 0.f, 0,0,0,0);

    // attention + refinement (3 iterations).  Ss aliases h2s (dead after V-MLP).
    for (int iter = 0; iter < 3; iter++) {
        gemm_tc<3,true,true><<<dim3(NN_/128, PP/128, BB), 256, SMEM_TRB>>>(
            Qs, Ks, lw, nullptr, Ss, NN_, DK_, DK_, scale,
            (size_t)PP*DK_, (size_t)NN_*DK_, (size_t)PP*NN_, (size_t)NN_);
        softmax4096<<<BB*PP, 256>>>(Ss);
        gemm_avk<<<dim3(1, PP/128, BB*KSPLIT), 256, SMEM_NN>>>(Ss, Vs, pt);
        reduce_avk<<<(BB*PP*DV_ + 255)/256, 256>>>(pt, pools);
        if (iter < 2) {
            gemm_tc<2,false,true><<<dim3(HH/128, BPQ/128, 1), 256, SMEM_NN>>>(
                pools, ws + WOFF_FW1, ref_b1, nullptr, h1s, HH, DV_, DV_, 0.f, 0,0,0,0);
            gemm_tc<1,false,false><<<dim3(DK_/128, BPQ/128, 1), 256, SMEM_NN>>>(
                h1s, ws + WOFF_FW2, ref_b2, dQ, nullptr, DK_, HH, HH, 0.f, 0,0,0,0);
            add_layernorm<<<BPQ, 128>>>(Q, Qs, dQ, ln_g, ln_b);
        }
    }

    // out = mlp2(pooled)
    gemm_tc<2,false,true><<<dim3(HH/128, BPQ/128, 1), 256, SMEM_NN>>>(
        pools, ws + WOFF_RW1, rho_b1, nullptr, h1s, HH, DV_, DV_, 0.f, 0,0,0,0);
    gemm_tc<1,false,false><<<dim3(DOUT_/128, BPQ/128, 1), 256, SMEM_NN>>>(
        h1s, ws + WOFF_RW2, rho_b2, out, nullptr, DOUT_, HH, HH, 0.f, 0,0,0,0);

    (void)in_sizes; (void)n_in; (void)out_size;
}